// round 9
// baseline (speedup 1.0000x reference)
#include <cuda_runtime.h>
#include <math.h>

// Problem dims (fixed by the dataset)
#define NB 4
#define CC 256
#define TT 16
#define HH 56
#define WW 56
#define KK 16
#define TP 8
#define HP 28
#define WP 28
#define PLANE (TT*HH*WW)        // 50176, channel stride in vw
#define OPLANE (TP*HP*WP)       // 6272, channel stride in out
#define SPLANE (HH*WW)          // 3136 spatial points per (n,t)

// Scratch: exp map, [N, T, H, W]
__device__ float g_emap[NB * TT * HH * WW];

__device__ __forceinline__ unsigned long long fma2(unsigned long long a,
                                                   unsigned long long b,
                                                   unsigned long long c) {
    unsigned long long d;
    asm("fma.rn.f32x2 %0, %1, %2, %3;" : "=l"(d) : "l"(a), "l"(b), "l"(c));
    return d;
}

__device__ __forceinline__ float lo32(unsigned long long v) {
    return __uint_as_float((unsigned)v);
}
__device__ __forceinline__ float hi32(unsigned long long v) {
    return __uint_as_float((unsigned)(v >> 32));
}

// ---------------------------------------------------------------------------
// Kernel 1: emap[n,t,h,w] = exp( max_k( sum_c w[n,k,c]*vw[n,c,t,h,w] ) / 16 )
// One packed spatial pair per lane, ALL 16 k's per lane (acc[16] ULL).
// Per warp per channel: 1 LDG.64 covering 32 distinct pairs (256B, zero
// address duplication) + 8 broadcast LDS.128 + 16 FMA2/lane. ~60 regs ->
// 4 blocks/SM (28 warps, 44% occ) with no spills.
// grid (7,16,4), block (32,7): 49 warps x 32 pairs = 1568 pairs per plane.
// ---------------------------------------------------------------------------
__global__ __launch_bounds__(224, 4) void emap_kernel(const float* __restrict__ vw,
                                                      const float* __restrict__ wmat) {
    __shared__ unsigned long long wsp[CC * KK];  // [c][k], each {s,s} packed

    const int n = blockIdx.z;
    const int t = blockIdx.y;
    const int tid = threadIdx.y * 32 + threadIdx.x;

    // Load weights for this n into smem, duplicated into both f32x2 halves.
    const float* wn = wmat + (size_t)n * KK * CC;   // layout [k][c]
    for (int j = tid; j < KK * CC; j += 224) {
        int k = j >> 8;        // j = k*256 + c
        int c = j & 255;
        unsigned int si = __float_as_uint(wn[j]);
        wsp[c * KK + k] = ((unsigned long long)si << 32) | si;
    }
    __syncthreads();

    const int lane = threadIdx.x;
    const int wg   = blockIdx.x * 7 + threadIdx.y;    // 0..48
    const int pair = wg * 32 + lane;                  // 0..1567

    size_t base = ((size_t)n * CC * TT + t) * SPLANE + 2 * pair;
    const unsigned long long* src = (const unsigned long long*)(vw + base);

    unsigned long long acc[KK];
#pragma unroll
    for (int k = 0; k < KK; k++) acc[k] = 0ull;

    const ulonglong2* wv = (const ulonglong2*)wsp;

    for (int c0 = 0; c0 < CC; c0 += 4) {
        unsigned long long x[4];
#pragma unroll
        for (int u = 0; u < 4; u++)
            x[u] = __ldg(src + (size_t)u * (PLANE / 2));
        src += 4 * (size_t)(PLANE / 2);
#pragma unroll
        for (int u = 0; u < 4; u++) {
#pragma unroll
            for (int j = 0; j < KK / 2; j++) {
                ulonglong2 wp = wv[(c0 + u) * (KK / 2) + j];
                acc[2 * j]     = fma2(wp.x, x[u], acc[2 * j]);
                acc[2 * j + 1] = fma2(wp.y, x[u], acc[2 * j + 1]);
            }
        }
    }

    float m0 = -3.4e38f, m1 = -3.4e38f;
#pragma unroll
    for (int k = 0; k < KK; k++) {
        m0 = fmaxf(m0, lo32(acc[k]));
        m1 = fmaxf(m1, hi32(acc[k]));
    }
    // sqrt(C) = 16 exactly
    size_t eidx = ((size_t)n * TT + t) * SPLANE + 2 * pair;
    *(float2*)(g_emap + eidx) = make_float2(expf(m0 * 0.0625f), expf(m1 * 0.0625f));
}

// ---------------------------------------------------------------------------
// Kernel 2 (unchanged from R8 — near DRAM roofline): lane owns output pair
// (2w2, 2w2+1); one LDG.128 per row per channel; the w-1 corner term comes
// from the left lane via one shfl_up per channel after the r-loop.
// grid (HP, TP, NB*2), block (32,8).
// ---------------------------------------------------------------------------
__global__ __launch_bounds__(256, 4) void pool_kernel(const float* __restrict__ vw,
                                                      float* __restrict__ out) {
    const int n     = blockIdx.z >> 1;
    const int chalf = blockIdx.z & 1;
    const int tp = blockIdx.y;
    const int hp = blockIdx.x;
    const int tid = threadIdx.y * 32 + threadIdx.x;

    __shared__ float4 wpk[9 * 14];   // {e[4w2], e[4w2+1], e[4w2+2], e[4w2+3]} per (r,w2)
    __shared__ float  wem[9 * 14];   // e[4w2-1]  (denominator only)
    __shared__ float  wrd[14 * 2];   // 1/denominator for outputs (2w2, 2w2+1)

    // Fill window-weight tables (126 items).
    if (tid < 126) {
        const int r  = tid / 14;
        const int w2 = tid - r * 14;
        const int dt = r / 3, dh = r - dt * 3;
        const int t = 2 * tp - 1 + dt;
        const int h = 2 * hp - 1 + dh;
        const bool rv = (t >= 0) && (h >= 0);
        const int tc = t > 0 ? t : 0;
        const int hc = h > 0 ? h : 0;
        const float* ep = g_emap + ((size_t)n * TT + tc) * SPLANE + (size_t)hc * WW;
        const int wb = 4 * w2;
        float em1 = (rv && wb > 0) ? ep[wb - 1] : 0.f;
        float e0 = rv ? ep[wb + 0] : 0.f;
        float e1 = rv ? ep[wb + 1] : 0.f;
        float e2 = rv ? ep[wb + 2] : 0.f;
        float e3 = rv ? ep[wb + 3] : 0.f;
        wpk[tid] = make_float4(e0, e1, e2, e3);
        wem[tid] = em1;
    }
    __syncthreads();
    if (tid < 28) {
        const int w2i = tid % 14;
        const int sel = tid / 14;
        float s = 0.f;
#pragma unroll
        for (int r = 0; r < 9; r++) {
            float4 f = wpk[r * 14 + w2i];
            s += sel ? (f.y + f.z + f.w) : (wem[r * 14 + w2i] + f.x + f.y);
        }
        wrd[w2i * 2 + sel] = 1.0f / s;
    }
    __syncthreads();

    const int lane = threadIdx.x;
    const int w2   = (lane & 15) < 14 ? (lane & 15) : 13;  // clamp
    const int csel = lane >> 4;                            // channel select 0/1
    const bool act = (lane & 15) < 14;

    const float rden0 = wrd[w2 * 2 + 0];
    const float rden1 = wrd[w2 * 2 + 1];

    int rowoff[9];
#pragma unroll
    for (int r = 0; r < 9; r++) {
        const int dt = r / 3, dh = r - dt * 3;
        const int t = 2 * tp - 1 + dt;
        const int h = 2 * hp - 1 + dh;
        const int tc = t > 0 ? t : 0;
        const int hc = h > 0 ? h : 0;
        rowoff[r] = (tc * HH + hc) * WW;
    }

    const float* basep = vw + (size_t)n * CC * PLANE + 4 * w2;
    float* outbase = out + (((size_t)n * CC * TP + tp) * HP + hp) * WP + 2 * w2;

    const int cbeg = chalf * (CC / 2);
    const ulonglong2* wpk2 = (const ulonglong2*)wpk;

    // 4 channels per warp-iteration: this lane handles cA=c0+2*csel, cB=cA+1.
    for (int c0 = cbeg + threadIdx.y * 4; c0 < cbeg + CC / 2; c0 += 32) {
        const int cA = c0 + 2 * csel;
        const float* pA = basep + (size_t)cA * PLANE;
        const float* pB = pA + PLANE;
        unsigned long long a0A = 0ull, a1A = 0ull, a0B = 0ull, a1B = 0ull;
        float sxA = 0.f, spA = 0.f, sxB = 0.f, spB = 0.f;
#pragma unroll
        for (int r = 0; r < 9; r++) {
            ulonglong2 xA = __ldg((const ulonglong2*)(pA + rowoff[r]));
            ulonglong2 xB = __ldg((const ulonglong2*)(pB + rowoff[r]));
            ulonglong2 wpr = wpk2[r * 14 + w2];   // .x = (e0,e1), .y = (e2,e3)
            a0A = fma2(wpr.x, xA.x, a0A);
            a1A = fma2(wpr.y, xA.y, a1A);
            a0B = fma2(wpr.x, xB.x, a0B);
            a1B = fma2(wpr.y, xB.y, a1B);
            sxA = fmaf(hi32(wpr.x), hi32(xA.x), sxA);   // e1*v1 -> own out1
            spA = fmaf(hi32(wpr.y), hi32(xA.y), spA);   // e3*v3 -> right nbr out0
            sxB = fmaf(hi32(wpr.x), hi32(xB.x), sxB);
            spB = fmaf(hi32(wpr.y), hi32(xB.y), spB);
        }
        float spAm = __shfl_up_sync(0xffffffffu, spA, 1);
        float spBm = __shfl_up_sync(0xffffffffu, spB, 1);
        if ((lane & 15) == 0) { spAm = 0.f; spBm = 0.f; }
        if (act) {
            float2 oA = make_float2((lo32(a0A) + hi32(a0A) + spAm) * rden0,
                                    (lo32(a1A) + hi32(a1A) + sxA) * rden1);
            float2 oB = make_float2((lo32(a0B) + hi32(a0B) + spBm) * rden0,
                                    (lo32(a1B) + hi32(a1B) + sxB) * rden1);
            *(float2*)(outbase + (size_t)cA * OPLANE) = oA;
            *(float2*)(outbase + (size_t)(cA + 1) * OPLANE) = oB;
        }
    }
}

extern "C" void kernel_launch(void* const* d_in, const int* in_sizes, int n_in,
                              void* d_out, int out_size) {
    const float* a0 = (const float*)d_in[0];
    const float* a1 = (const float*)d_in[1];
    // vw is the big tensor (51,380,224 elems); w is 16,384 elems.
    const float* vw   = (in_sizes[0] > in_sizes[1]) ? a0 : a1;
    const float* wmat = (in_sizes[0] > in_sizes[1]) ? a1 : a0;
    float* out = (float*)d_out;

    emap_kernel<<<dim3(7, TT, NB), dim3(32, 7)>>>(vw, wmat);
    pool_kernel<<<dim3(HP, TP, NB * 2), dim3(32, 8)>>>(vw, out);
}